// round 8
// baseline (speedup 1.0000x reference)
#include <cuda_runtime.h>
#include <cstdint>
#include <cfloat>

#define C_CL   8
#define E_EX   8
#define D_DIM  4096
#define NF4    (D_DIM / 4)     // row length in float4 units = 1024
#define NTOT   (C_CL * E_EX)
#define MAX_T  8192

// Scratch (no allocs allowed)
__device__ int g_cnt[C_CL];
__device__ int g_cluster[MAX_T];
__device__ int g_bucket[C_CL * MAX_T];
__device__ int g_order[MAX_T];

__global__ void zero_cnt_kernel() {
    if (threadIdx.x < C_CL) g_cnt[threadIdx.x] = 0;
}

// expert_ids robust read (int32 vs int64 delivery; content = arange(64))
__device__ __forceinline__ int read_eid(const void* p, int i) {
    const int* p32 = (const int*)p;
    if (__ldg(p32 + 1) == 0) return (int)__ldg(((const long long*)p) + i);
    return __ldg(p32 + i);
}

__device__ __forceinline__ void fma4(float acc[], const float4 xv, const float4 wv) {
    acc[0] = fmaf(xv.x, wv.x, acc[0]);
    acc[0] = fmaf(xv.y, wv.y, acc[0]);
    acc[0] = fmaf(xv.z, wv.z, acc[0]);
    acc[0] = fmaf(xv.w, wv.w, acc[0]);
}

// ============================================================================
// Pass A: cluster logits + argmax + bucket scatter.
// Block = 8 warps = 4 token-quads x 2 D-splits, 3 blocks/SM (scalar fp32
// accumulators keep regs <= 85). Dense LDG.128 outer product, one-deep x
// prefetch. All 4 x rows addressed off one base pointer (imm offsets).
// ============================================================================
__global__ void __launch_bounds__(256, 3) cluster_kernel(
    const float* __restrict__ x,
    const float* __restrict__ Wc)
{
    __shared__ float s_part[2][4][4][8];   // [split][quad][t][c]

    const int w    = threadIdx.x >> 5;
    const int lane = threadIdx.x & 31;
    const int qi   = w >> 1;               // token quad (0..3)
    const int s    = w & 1;                // D-split (0..1)
    const int tbase = blockIdx.x * 16 + qi * 4;

    const float4* xb = reinterpret_cast<const float4*>(x + (size_t)tbase * D_DIM);
    const float4* wr = reinterpret_cast<const float4*>(Wc);

    float acc[C_CL][4];
#pragma unroll
    for (int c = 0; c < C_CL; ++c)
#pragma unroll
        for (int t = 0; t < 4; ++t) acc[c][t] = 0.0f;

    int idx = s * 512 + lane;
    float4 x0 = __ldg(xb + 0 * NF4 + idx);
    float4 x1 = __ldg(xb + 1 * NF4 + idx);
    float4 x2 = __ldg(xb + 2 * NF4 + idx);
    float4 x3 = __ldg(xb + 3 * NF4 + idx);

    for (int it = 0; it < 16; ++it) {
        const int nidx = idx + ((it < 15) ? 32 : 0);
        float4 n0 = __ldg(xb + 0 * NF4 + nidx);
        float4 n1 = __ldg(xb + 1 * NF4 + nidx);
        float4 n2 = __ldg(xb + 2 * NF4 + nidx);
        float4 n3 = __ldg(xb + 3 * NF4 + nidx);
#pragma unroll
        for (int c = 0; c < C_CL; ++c) {
            float4 wv = __ldg(wr + c * NF4 + idx);
            fma4(&acc[c][0], x0, wv);
            fma4(&acc[c][1], x1, wv);
            fma4(&acc[c][2], x2, wv);
            fma4(&acc[c][3], x3, wv);
        }
        x0 = n0; x1 = n1; x2 = n2; x3 = n3;
        idx = nidx;
    }

    // Reduce c-by-c across the warp (4 live floats per step).
#pragma unroll
    for (int c = 0; c < C_CL; ++c) {
        float r0 = acc[c][0], r1 = acc[c][1], r2 = acc[c][2], r3 = acc[c][3];
#pragma unroll
        for (int d = 16; d >= 1; d >>= 1) {
            r0 += __shfl_xor_sync(0xffffffffu, r0, d);
            r1 += __shfl_xor_sync(0xffffffffu, r1, d);
            r2 += __shfl_xor_sync(0xffffffffu, r2, d);
            r3 += __shfl_xor_sync(0xffffffffu, r3, d);
        }
        if (lane == c * 4 + 0) s_part[s][qi][0][c] = r0;
        if (lane == c * 4 + 1) s_part[s][qi][1][c] = r1;
        if (lane == c * 4 + 2) s_part[s][qi][2][c] = r2;
        if (lane == c * 4 + 3) s_part[s][qi][3][c] = r3;
    }
    __syncthreads();

    // Combine 2 splits + argmax: 128 threads = 16 tok x 8 c.
    if (threadIdx.x < 128) {
        const int tl = threadIdx.x >> 3;    // token-local 0..15
        const int c  = threadIdx.x & 7;
        const int quad = tl >> 2, tt = tl & 3;
        float v = s_part[0][quad][tt][c] + s_part[1][quad][tt][c];
        int bi = c;
#pragma unroll
        for (int d = 1; d <= 4; d <<= 1) {
            float vo = __shfl_xor_sync(0xffffffffu, v, d);
            int   io = __shfl_xor_sync(0xffffffffu, bi, d);
            if (vo > v || (vo == v && io < bi)) { v = vo; bi = io; }  // first-max
        }
        if (c == 0) {
            const int t = blockIdx.x * 16 + tl;
            g_cluster[t] = bi;
            int pos = atomicAdd(&g_cnt[bi], 1);
            g_bucket[bi * MAX_T + pos] = t;
        }
    }
}

// ============================================================================
// Middle: compact gapped buckets into cluster-major flat order (8 blocks).
// ============================================================================
__global__ void __launch_bounds__(256) order_kernel() {
    const int c = blockIdx.x;
    int b = 0;
    for (int cc = 0; cc < c; ++cc) b += g_cnt[cc];
    const int n = g_cnt[c];
    for (int i = threadIdx.x; i < n; i += 256)
        g_order[b + i] = g_bucket[c * MAX_T + i];
}

// ============================================================================
// Pass B: expert logits for selected cluster + scatter into output row.
// Same dense structure; quads taken cluster-major from g_order so the 4
// tokens of a quad share expert weights (fast path). Boundary quads (rare)
// take a per-token serial path with tiny register footprint.
// ============================================================================
__global__ void __launch_bounds__(256, 3) expert_kernel(
    const float* __restrict__ x,
    const float* __restrict__ We,
    const void* __restrict__ eids,
    float* __restrict__ out)
{
    __shared__ float s_part[2][4][4][8];   // [split][quad][t][e]
    __shared__ float s_logit[16][8];
    __shared__ int   s_eid[16][8];
    __shared__ int   s_tok[16];
    __shared__ int   s_cl[16];

    const int w    = threadIdx.x >> 5;
    const int lane = threadIdx.x & 31;
    const int qi   = w >> 1;
    const int s    = w & 1;
    const int pbase = blockIdx.x * 16 + qi * 4;

    const int t0 = __ldg(&g_order[pbase + 0]);
    const int t1 = __ldg(&g_order[pbase + 1]);
    const int t2 = __ldg(&g_order[pbase + 2]);
    const int t3 = __ldg(&g_order[pbase + 3]);
    const int c0 = g_cluster[t0], c1 = g_cluster[t1];
    const int c2 = g_cluster[t2], c3 = g_cluster[t3];
    if (s == 0 && lane == 0) {
        s_tok[qi * 4 + 0] = t0; s_cl[qi * 4 + 0] = c0;
        s_tok[qi * 4 + 1] = t1; s_cl[qi * 4 + 1] = c1;
        s_tok[qi * 4 + 2] = t2; s_cl[qi * 4 + 2] = c2;
        s_tok[qi * 4 + 3] = t3; s_cl[qi * 4 + 3] = c3;
    }

    float acc[E_EX][4];
#pragma unroll
    for (int e = 0; e < E_EX; ++e)
#pragma unroll
        for (int t = 0; t < 4; ++t) acc[e][t] = 0.0f;

    if (c0 == c1 && c1 == c2 && c2 == c3) {
        // Fast path: one weight base for the whole quad; x prefetched 1 deep.
        const float4* wr = reinterpret_cast<const float4*>(
            We + (size_t)c0 * (E_EX * D_DIM));
        const float4* xp0 = reinterpret_cast<const float4*>(x + (size_t)t0 * D_DIM);
        const float4* xp1 = reinterpret_cast<const float4*>(x + (size_t)t1 * D_DIM);
        const float4* xp2 = reinterpret_cast<const float4*>(x + (size_t)t2 * D_DIM);
        const float4* xp3 = reinterpret_cast<const float4*>(x + (size_t)t3 * D_DIM);

        int idx = s * 512 + lane;
        float4 x0 = __ldg(xp0 + idx);
        float4 x1 = __ldg(xp1 + idx);
        float4 x2 = __ldg(xp2 + idx);
        float4 x3 = __ldg(xp3 + idx);
        for (int it = 0; it < 16; ++it) {
            const int nidx = idx + ((it < 15) ? 32 : 0);
            float4 n0 = __ldg(xp0 + nidx);
            float4 n1 = __ldg(xp1 + nidx);
            float4 n2 = __ldg(xp2 + nidx);
            float4 n3 = __ldg(xp3 + nidx);
#pragma unroll
            for (int e = 0; e < E_EX; ++e) {
                float4 wv = __ldg(wr + e * NF4 + idx);
                fma4(&acc[e][0], x0, wv);
                fma4(&acc[e][1], x1, wv);
                fma4(&acc[e][2], x2, wv);
                fma4(&acc[e][3], x3, wv);
            }
            x0 = n0; x1 = n1; x2 = n2; x3 = n3;
            idx = nidx;
        }
    } else {
        // Slow path: per-token serial (rare boundary quads; static acc index).
#pragma unroll
        for (int t = 0; t < 4; ++t) {
            const int tok = (t == 0) ? t0 : (t == 1) ? t1 : (t == 2) ? t2 : t3;
            const int cc  = (t == 0) ? c0 : (t == 1) ? c1 : (t == 2) ? c2 : c3;
            const float4* xp = reinterpret_cast<const float4*>(x + (size_t)tok * D_DIM);
            const float4* wp = reinterpret_cast<const float4*>(
                We + (size_t)cc * (E_EX * D_DIM));
            for (int it = 0; it < 16; ++it) {
                const int idx = s * 512 + it * 32 + lane;
                float4 xv = __ldg(xp + idx);
#pragma unroll
                for (int e = 0; e < E_EX; ++e) {
                    float4 wv = __ldg(wp + e * NF4 + idx);
                    fma4(&acc[e][t], xv, wv);
                }
            }
        }
    }

    // Reduce e-by-e.
#pragma unroll
    for (int e = 0; e < E_EX; ++e) {
        float r0 = acc[e][0], r1 = acc[e][1], r2 = acc[e][2], r3 = acc[e][3];
#pragma unroll
        for (int d = 16; d >= 1; d >>= 1) {
            r0 += __shfl_xor_sync(0xffffffffu, r0, d);
            r1 += __shfl_xor_sync(0xffffffffu, r1, d);
            r2 += __shfl_xor_sync(0xffffffffu, r2, d);
            r3 += __shfl_xor_sync(0xffffffffu, r3, d);
        }
        if (lane == e * 4 + 0) s_part[s][qi][0][e] = r0;
        if (lane == e * 4 + 1) s_part[s][qi][1][e] = r1;
        if (lane == e * 4 + 2) s_part[s][qi][2][e] = r2;
        if (lane == e * 4 + 3) s_part[s][qi][3][e] = r3;
    }
    __syncthreads();

    // Combine splits + fetch expert ids: 128 threads = 16 tok x 8 e.
    if (threadIdx.x < 128) {
        const int tl = threadIdx.x >> 3;
        const int e  = threadIdx.x & 7;
        const int quad = tl >> 2, tt = tl & 3;
        s_logit[tl][e] = s_part[0][quad][tt][e] + s_part[1][quad][tt][e];
        s_eid[tl][e]   = read_eid(eids, s_cl[tl] * E_EX + e);
    }
    __syncthreads();

    // Scatter: 256 threads = 16 tokens x 16 float4 (full 64-col rows).
    {
        const int tl = threadIdx.x >> 4;
        const int q  = threadIdx.x & 15;
        const int tok = s_tok[tl];
        float v[4];
#pragma unroll
        for (int j = 0; j < 4; ++j) {
            const int col = q * 4 + j;
            float val = -FLT_MAX;              // == jnp.finfo(float32).min
#pragma unroll
            for (int e = 0; e < E_EX; ++e)
                val = (s_eid[tl][e] == col) ? s_logit[tl][e] : val;
            v[j] = val;
        }
        reinterpret_cast<float4*>(out + (size_t)tok * NTOT)[q] =
            make_float4(v[0], v[1], v[2], v[3]);
    }
}

extern "C" void kernel_launch(void* const* d_in, const int* in_sizes, int n_in,
                              void* d_out, int out_size) {
    const float* x    = (const float*)d_in[0];
    const float* Wc   = (const float*)d_in[1];
    const float* We   = (const float*)d_in[2];
    const void*  eids = d_in[3];
    float*       out  = (float*)d_out;

    const int D = in_sizes[2] / in_sizes[3];     // 4096
    const int T = in_sizes[0] / D;               // 8192
    (void)n_in; (void)out_size;

    zero_cnt_kernel<<<1, 32>>>();

    const int blocks = T / 16;           // 16 tokens per block
    cluster_kernel<<<blocks, 256>>>(x, Wc);
    order_kernel<<<C_CL, 256>>>();
    expert_kernel<<<blocks, 256>>>(x, We, eids, out);
}

// round 9
// speedup vs baseline: 1.0878x; 1.0878x over previous
#include <cuda_runtime.h>
#include <cstdint>
#include <cfloat>

#define C_CL   8
#define E_EX   8
#define D_DIM  4096
#define NU2    (D_DIM / 4)     // row length in ulonglong2 (16B) units = 1024
#define NTOT   (C_CL * E_EX)
#define MAX_T  8192

// Scratch (no allocs allowed)
__device__ int g_cnt[C_CL];
__device__ int g_cluster[MAX_T];
__device__ int g_bucket[C_CL * MAX_T];
__device__ int g_order[MAX_T];

__global__ void zero_cnt_kernel() {
    if (threadIdx.x < C_CL) g_cnt[threadIdx.x] = 0;
}

// expert_ids robust read (int32 vs int64 delivery; content = arange(64))
__device__ __forceinline__ int read_eid(const void* p, int i) {
    const int* p32 = (const int*)p;
    if (__ldg(p32 + 1) == 0) return (int)__ldg(((const long long*)p) + i);
    return __ldg(p32 + i);
}

// ---- packed f32x2 helpers ----
__device__ __forceinline__ unsigned long long fma2(unsigned long long a,
                                                   unsigned long long b,
                                                   unsigned long long c) {
    unsigned long long d;
    asm("fma.rn.f32x2 %0, %1, %2, %3;" : "=l"(d) : "l"(a), "l"(b), "l"(c));
    return d;
}
__device__ __forceinline__ float sum2(unsigned long long v) {
    return __uint_as_float((unsigned)(v & 0xffffffffull)) +
           __uint_as_float((unsigned)(v >> 32));
}

// ============================================================================
// Pass A: cluster logits + argmax + bucket scatter.
// Block = 8 warps = 4 token-quads x 2 CLUSTER-halves (not D-splits).
// Warp: 4 tokens x 4 clusters x full 4096 dims, packed f32x2 accumulators
// (acc[4][4] = 32 regs) -> fits 3 blocks/SM WITH packed math.
// Dense LDG.128 outer product + one-deep x prefetch.
// ============================================================================
__global__ void __launch_bounds__(256, 3) cluster_kernel(
    const float* __restrict__ x,
    const float* __restrict__ Wc)
{
    __shared__ float s_part[2][4][4][4];   // [ehalf][quad][t][cg]

    const int w    = threadIdx.x >> 5;
    const int lane = threadIdx.x & 31;
    const int qi   = w >> 1;               // token quad (0..3)
    const int eh   = w & 1;                // cluster half (0..1)
    const int tbase = blockIdx.x * 16 + qi * 4;

    const ulonglong2* xb = reinterpret_cast<const ulonglong2*>(x + (size_t)tbase * D_DIM);
    const ulonglong2* wr = reinterpret_cast<const ulonglong2*>(Wc) + (size_t)(eh * 4) * NU2;

    unsigned long long acc[4][4];          // [cg][t] packed f32x2
#pragma unroll
    for (int cg = 0; cg < 4; ++cg)
#pragma unroll
        for (int t = 0; t < 4; ++t) acc[cg][t] = 0ull;

    int idx = lane;
    ulonglong2 x0 = __ldg(xb + 0 * NU2 + idx);
    ulonglong2 x1 = __ldg(xb + 1 * NU2 + idx);
    ulonglong2 x2 = __ldg(xb + 2 * NU2 + idx);
    ulonglong2 x3 = __ldg(xb + 3 * NU2 + idx);

    for (int it = 0; it < 32; ++it) {
        const int nidx = idx + ((it < 31) ? 32 : 0);
        ulonglong2 n0 = __ldg(xb + 0 * NU2 + nidx);
        ulonglong2 n1 = __ldg(xb + 1 * NU2 + nidx);
        ulonglong2 n2 = __ldg(xb + 2 * NU2 + nidx);
        ulonglong2 n3 = __ldg(xb + 3 * NU2 + nidx);
#pragma unroll
        for (int cg = 0; cg < 4; ++cg) {
            ulonglong2 wv = __ldg(wr + cg * NU2 + idx);
            acc[cg][0] = fma2(x0.x, wv.x, acc[cg][0]);
            acc[cg][0] = fma2(x0.y, wv.y, acc[cg][0]);
            acc[cg][1] = fma2(x1.x, wv.x, acc[cg][1]);
            acc[cg][1] = fma2(x1.y, wv.y, acc[cg][1]);
            acc[cg][2] = fma2(x2.x, wv.x, acc[cg][2]);
            acc[cg][2] = fma2(x2.y, wv.y, acc[cg][2]);
            acc[cg][3] = fma2(x3.x, wv.x, acc[cg][3]);
            acc[cg][3] = fma2(x3.y, wv.y, acc[cg][3]);
        }
        x0 = n0; x1 = n1; x2 = n2; x3 = n3;
        idx = nidx;
    }

    // Reduce cg-by-cg across the warp (4 live floats per step).
#pragma unroll
    for (int cg = 0; cg < 4; ++cg) {
        float r0 = sum2(acc[cg][0]), r1 = sum2(acc[cg][1]);
        float r2 = sum2(acc[cg][2]), r3 = sum2(acc[cg][3]);
#pragma unroll
        for (int d = 16; d >= 1; d >>= 1) {
            r0 += __shfl_xor_sync(0xffffffffu, r0, d);
            r1 += __shfl_xor_sync(0xffffffffu, r1, d);
            r2 += __shfl_xor_sync(0xffffffffu, r2, d);
            r3 += __shfl_xor_sync(0xffffffffu, r3, d);
        }
        if (lane == cg * 4 + 0) s_part[eh][qi][0][cg] = r0;
        if (lane == cg * 4 + 1) s_part[eh][qi][1][cg] = r1;
        if (lane == cg * 4 + 2) s_part[eh][qi][2][cg] = r2;
        if (lane == cg * 4 + 3) s_part[eh][qi][3][cg] = r3;
    }
    __syncthreads();

    // Argmax: 128 threads = 16 tok x 8 c (halves partition c, no addition).
    if (threadIdx.x < 128) {
        const int tl = threadIdx.x >> 3;    // token-local 0..15
        const int c  = threadIdx.x & 7;
        const int quad = tl >> 2, tt = tl & 3;
        float v = s_part[c >> 2][quad][tt][c & 3];
        int bi = c;
#pragma unroll
        for (int d = 1; d <= 4; d <<= 1) {
            float vo = __shfl_xor_sync(0xffffffffu, v, d);
            int   io = __shfl_xor_sync(0xffffffffu, bi, d);
            if (vo > v || (vo == v && io < bi)) { v = vo; bi = io; }  // first-max
        }
        if (c == 0) {
            const int t = blockIdx.x * 16 + tl;
            g_cluster[t] = bi;
            int pos = atomicAdd(&g_cnt[bi], 1);
            g_bucket[bi * MAX_T + pos] = t;
        }
    }
}

// ============================================================================
// Middle: compact gapped buckets into cluster-major flat order (8 blocks).
// ============================================================================
__global__ void __launch_bounds__(256) order_kernel() {
    const int c = blockIdx.x;
    int b = 0;
    for (int cc = 0; cc < c; ++cc) b += g_cnt[cc];
    const int n = g_cnt[c];
    for (int i = threadIdx.x; i < n; i += 256)
        g_order[b + i] = g_bucket[c * MAX_T + i];
}

// ============================================================================
// Pass B: expert logits for selected cluster + scatter into output row.
// Same quad x expert-half structure; quads taken cluster-major from g_order.
// ============================================================================
__global__ void __launch_bounds__(256, 3) expert_kernel(
    const float* __restrict__ x,
    const float* __restrict__ We,
    const void* __restrict__ eids,
    float* __restrict__ out)
{
    __shared__ float s_part[2][4][4][4];   // [ehalf][quad][t][eg]
    __shared__ float s_logit[16][8];
    __shared__ int   s_eid[16][8];
    __shared__ int   s_tok[16];
    __shared__ int   s_cl[16];

    const int w    = threadIdx.x >> 5;
    const int lane = threadIdx.x & 31;
    const int qi   = w >> 1;
    const int eh   = w & 1;
    const int pbase = blockIdx.x * 16 + qi * 4;

    const int t0 = __ldg(&g_order[pbase + 0]);
    const int t1 = __ldg(&g_order[pbase + 1]);
    const int t2 = __ldg(&g_order[pbase + 2]);
    const int t3 = __ldg(&g_order[pbase + 3]);
    const int c0 = g_cluster[t0], c1 = g_cluster[t1];
    const int c2 = g_cluster[t2], c3 = g_cluster[t3];
    if (eh == 0 && lane == 0) {
        s_tok[qi * 4 + 0] = t0; s_cl[qi * 4 + 0] = c0;
        s_tok[qi * 4 + 1] = t1; s_cl[qi * 4 + 1] = c1;
        s_tok[qi * 4 + 2] = t2; s_cl[qi * 4 + 2] = c2;
        s_tok[qi * 4 + 3] = t3; s_cl[qi * 4 + 3] = c3;
    }

    unsigned long long acc[4][4];          // [eg][t] packed f32x2
#pragma unroll
    for (int eg = 0; eg < 4; ++eg)
#pragma unroll
        for (int t = 0; t < 4; ++t) acc[eg][t] = 0ull;

    if (c0 == c1 && c1 == c2 && c2 == c3) {
        // Fast path: one weight base for the whole quad; x prefetched 1 deep.
        const ulonglong2* wr = reinterpret_cast<const ulonglong2*>(
            We + (size_t)c0 * (E_EX * D_DIM)) + (size_t)(eh * 4) * NU2;
        const ulonglong2* xp0 = reinterpret_cast<const ulonglong2*>(x + (size_t)t0 * D_DIM);
        const ulonglong2* xp1 = reinterpret_cast<const ulonglong2*>(x + (size_t)t1 * D_DIM);
        const ulonglong2* xp2 = reinterpret_cast<const ulonglong2*>(x + (size_t)t2 * D_DIM);
        const ulonglong2* xp3 = reinterpret_cast<const ulonglong2*>(x + (size_t)t3 * D_DIM);

        int idx = lane;
        ulonglong2 x0 = __ldg(xp0 + idx);
        ulonglong2 x1 = __ldg(xp1 + idx);
        ulonglong2 x2 = __ldg(xp2 + idx);
        ulonglong2 x3 = __ldg(xp3 + idx);
        for (int it = 0; it < 32; ++it) {
            const int nidx = idx + ((it < 31) ? 32 : 0);
            ulonglong2 n0 = __ldg(xp0 + nidx);
            ulonglong2 n1 = __ldg(xp1 + nidx);
            ulonglong2 n2 = __ldg(xp2 + nidx);
            ulonglong2 n3 = __ldg(xp3 + nidx);
#pragma unroll
            for (int eg = 0; eg < 4; ++eg) {
                ulonglong2 wv = __ldg(wr + eg * NU2 + idx);
                acc[eg][0] = fma2(x0.x, wv.x, acc[eg][0]);
                acc[eg][0] = fma2(x0.y, wv.y, acc[eg][0]);
                acc[eg][1] = fma2(x1.x, wv.x, acc[eg][1]);
                acc[eg][1] = fma2(x1.y, wv.y, acc[eg][1]);
                acc[eg][2] = fma2(x2.x, wv.x, acc[eg][2]);
                acc[eg][2] = fma2(x2.y, wv.y, acc[eg][2]);
                acc[eg][3] = fma2(x3.x, wv.x, acc[eg][3]);
                acc[eg][3] = fma2(x3.y, wv.y, acc[eg][3]);
            }
            x0 = n0; x1 = n1; x2 = n2; x3 = n3;
            idx = nidx;
        }
    } else {
        // Slow path: per-token serial (rare boundary quads).
#pragma unroll
        for (int t = 0; t < 4; ++t) {
            const int tok = (t == 0) ? t0 : (t == 1) ? t1 : (t == 2) ? t2 : t3;
            const int cc  = (t == 0) ? c0 : (t == 1) ? c1 : (t == 2) ? c2 : c3;
            const ulonglong2* xp = reinterpret_cast<const ulonglong2*>(x + (size_t)tok * D_DIM);
            const ulonglong2* wp = reinterpret_cast<const ulonglong2*>(
                We + (size_t)cc * (E_EX * D_DIM)) + (size_t)(eh * 4) * NU2;
            for (int it = 0; it < 32; ++it) {
                const int idx = it * 32 + lane;
                ulonglong2 xv = __ldg(xp + idx);
#pragma unroll
                for (int eg = 0; eg < 4; ++eg) {
                    ulonglong2 wv = __ldg(wp + eg * NU2 + idx);
                    acc[eg][t] = fma2(xv.x, wv.x, acc[eg][t]);
                    acc[eg][t] = fma2(xv.y, wv.y, acc[eg][t]);
                }
            }
        }
    }

    // Reduce eg-by-eg.
#pragma unroll
    for (int eg = 0; eg < 4; ++eg) {
        float r0 = sum2(acc[eg][0]), r1 = sum2(acc[eg][1]);
        float r2 = sum2(acc[eg][2]), r3 = sum2(acc[eg][3]);
#pragma unroll
        for (int d = 16; d >= 1; d >>= 1) {
            r0 += __shfl_xor_sync(0xffffffffu, r0, d);
            r1 += __shfl_xor_sync(0xffffffffu, r1, d);
            r2 += __shfl_xor_sync(0xffffffffu, r2, d);
            r3 += __shfl_xor_sync(0xffffffffu, r3, d);
        }
        if (lane == eg * 4 + 0) s_part[eh][qi][0][eg] = r0;
        if (lane == eg * 4 + 1) s_part[eh][qi][1][eg] = r1;
        if (lane == eg * 4 + 2) s_part[eh][qi][2][eg] = r2;
        if (lane == eg * 4 + 3) s_part[eh][qi][3][eg] = r3;
    }
    __syncthreads();

    // Gather halves + fetch expert ids: 128 threads = 16 tok x 8 e.
    if (threadIdx.x < 128) {
        const int tl = threadIdx.x >> 3;
        const int e  = threadIdx.x & 7;
        const int quad = tl >> 2, tt = tl & 3;
        s_logit[tl][e] = s_part[e >> 2][quad][tt][e & 3];
        s_eid[tl][e]   = read_eid(eids, s_cl[tl] * E_EX + e);
    }
    __syncthreads();

    // Scatter: 256 threads = 16 tokens x 16 float4 (full 64-col rows).
    {
        const int tl = threadIdx.x >> 4;
        const int q  = threadIdx.x & 15;
        const int tok = s_tok[tl];
        float v[4];
#pragma unroll
        for (int j = 0; j < 4; ++j) {
            const int col = q * 4 + j;
            float val = -FLT_MAX;              // == jnp.finfo(float32).min
#pragma unroll
            for (int e = 0; e < E_EX; ++e)
                val = (s_eid[tl][e] == col) ? s_logit[tl][e] : val;
            v[j] = val;
        }
        reinterpret_cast<float4*>(out + (size_t)tok * NTOT)[q] =
            make_float4(v[0], v[1], v[2], v[3]);
    }
}

extern "C" void kernel_launch(void* const* d_in, const int* in_sizes, int n_in,
                              void* d_out, int out_size) {
    const float* x    = (const float*)d_in[0];
    const float* Wc   = (const float*)d_in[1];
    const float* We   = (const float*)d_in[2];
    const void*  eids = d_in[3];
    float*       out  = (float*)d_out;

    const int D = in_sizes[2] / in_sizes[3];     // 4096
    const int T = in_sizes[0] / D;               // 8192
    (void)n_in; (void)out_size;

    zero_cnt_kernel<<<1, 32>>>();

    const int blocks = T / 16;           // 16 tokens per block
    cluster_kernel<<<blocks, 256>>>(x, Wc);
    order_kernel<<<C_CL, 256>>>();
    expert_kernel<<<blocks, 256>>>(x, We, eids, out);
}